// round 15
// baseline (speedup 1.0000x reference)
#include <cuda_runtime.h>
#include <cuda_bf16.h>
#include <math.h>
#include <stdint.h>

#define Bb 8
#define Ll 4096
#define Cc 256
#define E2 1024
#define DI 512
#define NKP 48   // DT_RANK + 2*D_STATE
#define NS 16    // D_STATE
#define NPART 16
#define PLEN 256
#define SCH 64

// ---------------- scratch (static device allocations) ----------------
__device__ __nv_bfloat16 g_xnh[Bb * Ll * Cc];
__device__ __nv_bfloat16 g_xnl[Bb * Ll * Cc];
__device__ float g_xt[Bb * Ll * Cc];
__device__ float g_xz[Bb * E2 * Ll];
__device__ float g_xc[2][Bb * DI * Ll];           // conv+silu out per dir (b,d,l)
__device__ float g_xdbl[2][Bb * NKP * Ll];
__device__ float g_y[2][Bb * Ll * DI];            // scan out transposed (b,l,d)
__device__ float g_hp[2 * Bb * NPART * DI * NS * 2];
__device__ float g_h0[2 * Bb * NPART * DI * NS];
__device__ float g_xm[Bb * Ll * Cc];
__device__ __nv_bfloat16 g_xmh[Bb * Ll * Cc];
__device__ __nv_bfloat16 g_xml[Bb * Ll * Cc];
__device__ __nv_bfloat16 g_wih[E2 * Cc], g_wil[E2 * Cc];
__device__ __nv_bfloat16 g_woh[Cc * DI], g_wol[Cc * DI];
__device__ __nv_bfloat16 g_wph[Cc * Cc], g_wpl[Cc * Cc];

__device__ __forceinline__ float siluf(float v) {
    return v / (1.f + __expf(-v));
}

__device__ __forceinline__ uint32_t smem_u32(const void* p) {
    uint32_t a;
    asm("{ .reg .u64 t; cvta.to.shared.u64 t, %1; cvt.u32.u64 %0, t; }"
        : "=r"(a) : "l"(p));
    return a;
}

#define CPA16(dst, src) \
    asm volatile("cp.async.cg.shared.global [%0], [%1], 16;" :: "r"(dst), "l"(src))
#define CPA_COMMIT() asm volatile("cp.async.commit_group;" ::: "memory")
#define CPA_WAIT1() asm volatile("cp.async.wait_group 1;" ::: "memory")
#define CPA_WAIT0() asm volatile("cp.async.wait_group 0;" ::: "memory")

#define LDSM4(r, addr) \
    asm volatile("ldmatrix.sync.aligned.m8n8.x4.shared.b16 {%0,%1,%2,%3}, [%4];" \
        : "=r"((r)[0]), "=r"((r)[1]), "=r"((r)[2]), "=r"((r)[3]) : "r"(addr))

#define MMA16816(c, a, b0, b1) \
    asm volatile("mma.sync.aligned.m16n8k16.row.col.f32.bf16.bf16.f32 " \
        "{%0,%1,%2,%3},{%4,%5,%6,%7},{%8,%9},{%0,%1,%2,%3};" \
        : "+f"((c)[0]), "+f"((c)[1]), "+f"((c)[2]), "+f"((c)[3]) \
        : "r"((a)[0]), "r"((a)[1]), "r"((a)[2]), "r"((a)[3]), "r"(b0), "r"(b1))

// ---------------- weight fp32 -> bf16 hi/lo split ------------------------
__global__ void wsplit_k(const float* __restrict__ w, __nv_bfloat16* __restrict__ h,
                         __nv_bfloat16* __restrict__ l, int n) {
    int i = blockIdx.x * 256 + threadIdx.x;
    if (i < n) {
        float v = w[i];
        __nv_bfloat16 hh = __float2bfloat16(v);
        h[i] = hh;
        l[i] = __float2bfloat16(v - __bfloat162float(hh));
    }
}

// ---------------- LayerNorm 1 ------------------------------------------
__global__ void ln1_k(const float* __restrict__ x, const float* __restrict__ g,
                      const float* __restrict__ bta, __nv_bfloat16* __restrict__ xnh,
                      __nv_bfloat16* __restrict__ xnl, float* __restrict__ xt) {
    __shared__ float tile[256][33];
    __shared__ float red1[8][33];
    __shared__ float red2[8][33];
    __shared__ float smean[32], srstd[32];
    int b = blockIdx.y;
    int l0 = blockIdx.x << 5;
    int t = threadIdx.x;
    int lx = t & 31, cy = t >> 5;
    long base = (long)b * Cc * Ll + l0;
    float s = 0.f, sq = 0.f;
#pragma unroll
    for (int q = 0; q < 32; q++) {
        int c = (cy << 5) + q;
        float v = x[base + (long)c * Ll + lx];
        tile[c][lx] = v;
        s += v;
        sq += v * v;
    }
    red1[cy][lx] = s;
    red2[cy][lx] = sq;
    __syncthreads();
    if (t < 32) {
        float ts = 0.f, tq = 0.f;
#pragma unroll
        for (int p = 0; p < 8; p++) { ts += red1[p][t]; tq += red2[p][t]; }
        float mean = ts * (1.f / 256.f);
        float var = tq * (1.f / 256.f) - mean * mean;
        smean[t] = mean;
        srstd[t] = rsqrtf(var + 1e-5f);
    }
    __syncthreads();
    float gv = g[t], bv = bta[t];
#pragma unroll
    for (int li = 0; li < 32; li++) {
        float raw = tile[t][li];
        long o = ((long)b * Ll + l0 + li) * Cc + t;
        xt[o] = raw;
        float vn = (raw - smean[li]) * srstd[li] * gv + bv;
        __nv_bfloat16 h = __float2bfloat16(vn);
        xnh[o] = h;
        xnl[o] = __float2bfloat16(vn - __bfloat162float(h));
    }
}

// ---------------- LayerNorm 2 ------------------------------------------
__global__ void ln2_k(const float* __restrict__ xm, const float* __restrict__ g,
                      const float* __restrict__ bta, __nv_bfloat16* __restrict__ oh,
                      __nv_bfloat16* __restrict__ ol) {
    int row = blockIdx.x, t = threadIdx.x;
    long o = (long)row * Cc + t;
    float v = xm[o];
    float s = v, sq = v * v;
#pragma unroll
    for (int off = 16; off; off >>= 1) {
        s += __shfl_xor_sync(0xffffffffu, s, off);
        sq += __shfl_xor_sync(0xffffffffu, sq, off);
    }
    __shared__ float as_[8], aq_[8];
    if ((t & 31) == 0) { as_[t >> 5] = s; aq_[t >> 5] = sq; }
    __syncthreads();
    float ts = 0.f, tq = 0.f;
#pragma unroll
    for (int p = 0; p < 8; p++) { ts += as_[p]; tq += aq_[p]; }
    float mean = ts * (1.f / 256.f);
    float rs = rsqrtf(tq * (1.f / 256.f) - mean * mean + 1e-5f);
    float vn = (v - mean) * rs * g[t] + bta[t];
    __nv_bfloat16 h = __float2bfloat16(vn);
    oh[o] = h;
    ol[o] = __float2bfloat16(vn - __bfloat162float(h));
}

// ---------------- conv+silu: one (b,d) row per block (R6, 33us) ---------
__global__ __launch_bounds__(256) void conv_silu_k(
    const float* __restrict__ xz,
    const float* __restrict__ cwf, const float* __restrict__ cbf,
    const float* __restrict__ cwr, const float* __restrict__ cbr,
    float* __restrict__ xcf, float* __restrict__ xcr) {
    __shared__ float row[Ll];
    int d = blockIdx.x, b = blockIdx.y;
    int t = threadIdx.x;
    const float* xi = xz + ((long)b * E2 + d) * Ll;
#pragma unroll
    for (int q = 0; q < 4; q++) {
        int f = q * 256 + t;
        *reinterpret_cast<float4*>(&row[f * 4]) =
            *reinterpret_cast<const float4*>(&xi[f * 4]);
    }
    float wf0 = cwf[d * 4 + 0], wf1 = cwf[d * 4 + 1], wf2 = cwf[d * 4 + 2], wf3 = cwf[d * 4 + 3];
    float wr0 = cwr[d * 4 + 0], wr1 = cwr[d * 4 + 1], wr2 = cwr[d * 4 + 2], wr3 = cwr[d * 4 + 3];
    float bf = cbf[d], br = cbr[d];
    __syncthreads();
    long ob = ((long)b * DI + d) * Ll;
#pragma unroll
    for (int q = 0; q < 4; q++) {
        int l0 = (q * 256 + t) * 4;
        float4 of, orv;
        float* ofp = &of.x;
        float* orp = &orv.x;
#pragma unroll
        for (int u = 0; u < 4; u++) {
            int l = l0 + u;
            float sf = bf + wf3 * row[l];
            if (l - 3 >= 0) sf += wf0 * row[l - 3];
            if (l - 2 >= 0) sf += wf1 * row[l - 2];
            if (l - 1 >= 0) sf += wf2 * row[l - 1];
            ofp[u] = siluf(sf);
            float sr = br + wr3 * row[l];
            if (l + 3 < Ll) sr += wr0 * row[l + 3];
            if (l + 2 < Ll) sr += wr1 * row[l + 2];
            if (l + 1 < Ll) sr += wr2 * row[l + 1];
            orp[u] = siluf(sr);
        }
        *reinterpret_cast<float4*>(&xcf[ob + l0]) = of;
        *reinterpret_cast<float4*>(&xcr[ob + l0]) = orv;
    }
}

// ======= mma.sync split-bf16 GEMM, 2-stage pipeline =====================
// OUTT: C at (m/L)*(N*L)+n*L+(m%L); else row-major C[m*N+n].
// EPI: 0 none | 2 +epv[n] | 3 + eps[0]*epx[m*N+n]
// AYS: A built in-loader from fp32 Y0+Y1 (sum + bf16 hi/lo split).
template <bool OUTT, int EPI, bool AYS>
__global__ __launch_bounds__(256) void tc_gemm(
    const __nv_bfloat16* __restrict__ Ah, const __nv_bfloat16* __restrict__ Al,
    const __nv_bfloat16* __restrict__ Wh, const __nv_bfloat16* __restrict__ Wl,
    const float* __restrict__ Y0, const float* __restrict__ Y1,
    float* __restrict__ Co, int N, int K,
    const float* __restrict__ epv, const float* __restrict__ epx,
    const float* __restrict__ eps) {
    extern __shared__ __align__(16) char smraw[];
    float* Cs = (float*)smraw;
    int t = threadIdx.x;
    int lane = t & 31, wid = t >> 5;
    int wm = wid >> 2, wn = wid & 3;
    int m0 = blockIdx.x * 128, n0 = blockIdx.y * 128;
    uint32_t sbase = smem_u32(smraw);

    auto ldst = [&](int stage, int k0) {
#pragma unroll
        for (int q = 0; q < 2; q++) {
            int unit = t + q * 256;
            int r = unit >> 2, c = unit & 3;
            uint32_t d = sbase + stage * 32768 + r * 64 + 16 * (c ^ ((r >> 1) & 3));
            long goff = (long)r * K + k0 + c * 8;
            CPA16(d + 16384, Wh + (long)n0 * K + goff);
            CPA16(d + 24576, Wl + (long)n0 * K + goff);
            if (!AYS) {
                CPA16(d, Ah + (long)m0 * K + goff);
                CPA16(d + 8192, Al + (long)m0 * K + goff);
            }
        }
        CPA_COMMIT();
        if (AYS) {
#pragma unroll
            for (int q = 0; q < 2; q++) {
                int unit = t + q * 256;
                int r = unit >> 2, c = unit & 3;
                int off = stage * 32768 + r * 64 + 16 * (c ^ ((r >> 1) & 3));
                const float* p0 = Y0 + (long)(m0 + r) * K + k0 + c * 8;
                const float* p1 = Y1 + (long)(m0 + r) * K + k0 + c * 8;
                float4 a0 = *reinterpret_cast<const float4*>(p0);
                float4 a1 = *reinterpret_cast<const float4*>(p0 + 4);
                float4 b0 = *reinterpret_cast<const float4*>(p1);
                float4 b1 = *reinterpret_cast<const float4*>(p1 + 4);
                float v[8] = {a0.x + b0.x, a0.y + b0.y, a0.z + b0.z, a0.w + b0.w,
                              a1.x + b1.x, a1.y + b1.y, a1.z + b1.z, a1.w + b1.w};
                uint4 hu, lu;
                uint32_t* hp = &hu.x;
                uint32_t* lp = &lu.x;
#pragma unroll
                for (int j = 0; j < 4; j++) {
                    float x1 = v[2 * j], x2 = v[2 * j + 1];
                    __nv_bfloat16 h1 = __float2bfloat16(x1), h2 = __float2bfloat16(x2);
                    __nv_bfloat162 hh = __halves2bfloat162(h1, h2);
                    hp[j] = *reinterpret_cast<uint32_t*>(&hh);
                    __nv_bfloat162 llv = __halves2bfloat162(
                        __float2bfloat16(x1 - __bfloat162float(h1)),
                        __float2bfloat16(x2 - __bfloat162float(h2)));
                    lp[j] = *reinterpret_cast<uint32_t*>(&llv);
                }
                *reinterpret_cast<uint4*>(smraw + off) = hu;
                *reinterpret_cast<uint4*>(smraw + off + 8192) = lu;
            }
        }
    };

    float acc[4][4][4];
#pragma unroll
    for (int i = 0; i < 4; i++)
#pragma unroll
        for (int j = 0; j < 4; j++)
#pragma unroll
            for (int q = 0; q < 4; q++) acc[i][j][q] = 0.f;

    int NC = K >> 5;
    ldst(0, 0);
    int row_l = (lane & 7) + ((lane >> 3) & 1) * 8;
    int khalf = (lane >> 4) & 1;
    for (int it = 0; it < NC; it++) {
        if (it + 1 < NC) { ldst((it + 1) & 1, (it + 1) << 5); CPA_WAIT1(); }
        else CPA_WAIT0();
        __syncthreads();
        uint32_t abase = sbase + (it & 1) * 32768;
#pragma unroll
        for (int kk = 0; kk < 2; kk++) {
            uint32_t ah[4][4], al[4][4];
#pragma unroll
            for (int mt = 0; mt < 4; mt++) {
                int r = wm * 64 + mt * 16 + row_l;
                uint32_t ad = abase + r * 64 + 16 * ((kk * 2 + khalf) ^ ((r >> 1) & 3));
                LDSM4(ah[mt], ad);
                LDSM4(al[mt], ad + 8192);
            }
            uint32_t bh[4][2], bl[4][2];
#pragma unroll
            for (int np = 0; np < 2; np++) {
                int r = wn * 32 + np * 16 + row_l;
                uint32_t bd = abase + 16384 + r * 64 + 16 * ((kk * 2 + khalf) ^ ((r >> 1) & 3));
                uint32_t tmp[4];
                LDSM4(tmp, bd);
                bh[np * 2][0] = tmp[0]; bh[np * 2][1] = tmp[2];
                bh[np * 2 + 1][0] = tmp[1]; bh[np * 2 + 1][1] = tmp[3];
                LDSM4(tmp, bd + 8192);
                bl[np * 2][0] = tmp[0]; bl[np * 2][1] = tmp[2];
                bl[np * 2 + 1][0] = tmp[1]; bl[np * 2 + 1][1] = tmp[3];
            }
#pragma unroll
            for (int mt = 0; mt < 4; mt++)
#pragma unroll
                for (int nt = 0; nt < 4; nt++) {
                    MMA16816(acc[mt][nt], ah[mt], bh[nt][0], bh[nt][1]);
                    MMA16816(acc[mt][nt], ah[mt], bl[nt][0], bl[nt][1]);
                    MMA16816(acc[mt][nt], al[mt], bh[nt][0], bh[nt][1]);
                }
        }
        __syncthreads();
    }

#pragma unroll
    for (int mt = 0; mt < 4; mt++) {
        int m = wm * 64 + mt * 16 + (lane >> 2);
#pragma unroll
        for (int nt = 0; nt < 4; nt++) {
            int n = wn * 32 + nt * 8 + (lane & 3) * 2;
            Cs[n * 132 + m] = acc[mt][nt][0];
            Cs[(n + 1) * 132 + m] = acc[mt][nt][1];
            Cs[n * 132 + m + 8] = acc[mt][nt][2];
            Cs[(n + 1) * 132 + m + 8] = acc[mt][nt][3];
        }
    }
    __syncthreads();

    if (OUTT) {
        long bO = (long)(m0 / Ll) * ((long)N * Ll) + (m0 % Ll);
#pragma unroll
        for (int q = 0; q < 16; q++) {
            int nr = (t >> 5) + q * 8;
            int mc = lane * 4;
            float4 v = *reinterpret_cast<const float4*>(&Cs[nr * 132 + mc]);
            int nn = n0 + nr;
            if (EPI == 2) {
                float bv = epv[nn];
                v.x += bv; v.y += bv; v.z += bv; v.w += bv;
            }
            *reinterpret_cast<float4*>(Co + bO + (long)nn * Ll + mc) = v;
        }
    } else {
        float ss = (EPI == 3) ? eps[0] : 0.f;
        int row = t >> 1, ch2 = (t & 1) * 64;
#pragma unroll
        for (int f = 0; f < 16; f++) {
            int c = ch2 + f * 4;
            float4 v;
            v.x = Cs[(c + 0) * 132 + row];
            v.y = Cs[(c + 1) * 132 + row];
            v.z = Cs[(c + 2) * 132 + row];
            v.w = Cs[(c + 3) * 132 + row];
            long go = (long)(m0 + row) * N + n0 + c;
            if (EPI == 3) {
                float4 sk = *reinterpret_cast<const float4*>(epx + go);
                v.x = fmaf(ss, sk.x, v.x); v.y = fmaf(ss, sk.y, v.y);
                v.z = fmaf(ss, sk.z, v.z); v.w = fmaf(ss, sk.w, v.w);
            }
            *reinterpret_cast<float4*>(Co + go) = v;
        }
    }
}

// ---------------- FFMA GEMM (x_proj only) -------------------------------
template <bool ACOL, bool OUTT, int EPI, int TM, int TN, bool ASUM>
__global__ __launch_bounds__(256, 2) void gemm_k(
    const float* __restrict__ A, const float* __restrict__ A2,
    const float* __restrict__ W, const float* __restrict__ W1,
    float* __restrict__ Co, int N, int K, long sAb, long sAk,
    long sAd, long sCd,
    const float* __restrict__ epv, const float* __restrict__ epv1,
    const float* __restrict__ epx, const float* __restrict__ eps) {
    constexpr int RM = TM / 16, RN = TN / 16;
    constexpr int TMp = TM + 4, TNp = TN + 4;
    constexpr int ASZ = 2 * 16 * TMp, BSZ = 2 * 16 * TNp;
    constexpr int CSZ = 64 * TMp;
    constexpr int SMF = (ASZ + BSZ > CSZ) ? (ASZ + BSZ) : CSZ;
    __shared__ __align__(16) float sm[SMF];
    float* Asm = sm;
    float* Bsm = sm + ASZ;

    int t = threadIdx.x;
    int m0 = blockIdx.x * TM, n0 = blockIdx.y * TN;
    int dir = blockIdx.z;
    A += (long)dir * sAd;
    if (ASUM) A2 += (long)dir * sAd;
    if (dir) W = W1;
    Co += (long)dir * sCd;
    const float* ep = (dir && epv1) ? epv1 : epv;
    int tx = t & 15, ty = t >> 4;

    float4 ra[2], rb[2];
    constexpr int NB = TN / 64;

    auto ldgA = [&](int k0) {
        if (ACOL) {
            long base = (long)(m0 / Ll) * sAb + (m0 % Ll);
            int k = t >> 5, col = (t & 31) << 2;
#pragma unroll
            for (int q = 0; q < 2; q++) {
                long off = base + (long)(k0 + k + 8 * q) * sAk + col;
                ra[q] = *reinterpret_cast<const float4*>(A + off);
                if (ASUM) {
                    float4 r2 = *reinterpret_cast<const float4*>(A2 + off);
                    ra[q].x += r2.x; ra[q].y += r2.y; ra[q].z += r2.z; ra[q].w += r2.w;
                }
            }
        } else {
            int m = t >> 2, kq = (t & 3) << 2;
#pragma unroll
            for (int q = 0; q < 2; q++)
                ra[q] = *reinterpret_cast<const float4*>(A + (long)(m0 + m + 64 * q) * K + k0 + kq);
        }
    };
    auto stsA = [&](int buf) {
        if (ACOL) {
            int k = t >> 5, col = (t & 31) << 2;
#pragma unroll
            for (int q = 0; q < 2; q++)
                *reinterpret_cast<float4*>(&Asm[(buf * 16 + k + 8 * q) * TMp + col]) = ra[q];
        } else {
            int m = t >> 2, kq = (t & 3) << 2;
#pragma unroll
            for (int q = 0; q < 2; q++) {
                float* rp = &ra[q].x;
#pragma unroll
                for (int j = 0; j < 4; j++)
                    Asm[(buf * 16 + kq + j) * TMp + m + 64 * q] = rp[j];
            }
        }
    };
    auto ldgB = [&](int k0) {
        int n = t >> 2, kq = (t & 3) << 2;
#pragma unroll
        for (int q = 0; q < NB; q++) {
            int nn = n0 + n + 64 * q;
            rb[q] = (nn < N) ? *reinterpret_cast<const float4*>(W + (long)nn * K + k0 + kq)
                             : make_float4(0.f, 0.f, 0.f, 0.f);
        }
    };
    auto stsB = [&](int buf) {
        int n = t >> 2, kq = (t & 3) << 2;
#pragma unroll
        for (int q = 0; q < NB; q++) {
            float* rp = &rb[q].x;
#pragma unroll
            for (int j = 0; j < 4; j++)
                Bsm[(buf * 16 + kq + j) * TNp + n + 64 * q] = rp[j];
        }
    };

    float acc[RM][RN] = {};
    int NIT = K >> 4;
    ldgA(0); ldgB(0); stsA(0); stsB(0);
    __syncthreads();
    int buf = 0;
    for (int it = 0; it < NIT; it++) {
        bool more = (it + 1 < NIT);
        if (more) { ldgA((it + 1) << 4); ldgB((it + 1) << 4); }
#pragma unroll
        for (int kk = 0; kk < 16; kk++) {
            float ar[RM], br[RN];
#pragma unroll
            for (int q = 0; q < RM / 4; q++)
                *reinterpret_cast<float4*>(&ar[4 * q]) =
                    *reinterpret_cast<const float4*>(&Asm[(buf * 16 + kk) * TMp + ty * 4 + 64 * q]);
#pragma unroll
            for (int q = 0; q < RN / 4; q++)
                *reinterpret_cast<float4*>(&br[4 * q]) =
                    *reinterpret_cast<const float4*>(&Bsm[(buf * 16 + kk) * TNp + tx * 4 + 64 * q]);
#pragma unroll
            for (int i = 0; i < RM; i++)
#pragma unroll
                for (int j = 0; j < RN; j++)
                    acc[i][j] = fmaf(ar[i], br[j], acc[i][j]);
        }
        if (more) { stsA(buf ^ 1); stsB(buf ^ 1); }
        __syncthreads();
        buf ^= 1;
    }

    if constexpr (OUTT) {
        float* Cs = sm;
        long bO = (long)(m0 / Ll) * ((long)N * Ll) + (m0 % Ll);
        constexpr int NCH = TN / 64;
#pragma unroll
        for (int h = 0; h < NCH; h++) {
#pragma unroll
            for (int ii = 0; ii < RM; ii++) {
                int ml = (ii >> 2) * 64 + ty * 4 + (ii & 3);
#pragma unroll
                for (int jj = 0; jj < RN; jj++) {
                    if (NCH == 1 || (jj >> 2) == h) {
                        int nr = tx * 4 + (jj & 3);
                        float v = acc[ii][jj];
                        int nn = n0 + h * 64 + nr;
                        int nc = nn < N ? nn : 0;
                        if (EPI == 1) {
                            v += ep[nc];
                            v = (v > 20.f) ? v : log1pf(__expf(v));
                        } else if (EPI == 2) {
                            v += ep[nc];
                        }
                        Cs[nr * TMp + ml] = v;
                    }
                }
            }
            __syncthreads();
#pragma unroll
            for (int q = 0; q < (64 * TM) / 1024; q++) {
                int nr = (t >> 5) + q * 8;
                int mc = (t & 31) * 4;
                int nn = n0 + h * 64 + nr;
                if (nn < N)
                    *reinterpret_cast<float4*>(Co + bO + (long)nn * Ll + mc) =
                        *reinterpret_cast<const float4*>(&Cs[nr * TMp + mc]);
            }
            if (h + 1 < NCH) __syncthreads();
        }
    } else {
        float ssc = (EPI == 3) ? eps[0] : 0.f;
#pragma unroll
        for (int ii = 0; ii < RM; ii++) {
            int m = m0 + (ii >> 2) * 64 + ty * 4 + (ii & 3);
#pragma unroll
            for (int jh = 0; jh < RN / 4; jh++) {
                int nn0 = n0 + jh * 64 + tx * 4;
                float4 v;
                float* vp = &v.x;
#pragma unroll
                for (int j = 0; j < 4; j++) {
                    float vv = acc[ii][jh * 4 + j];
                    if (EPI == 3) vv = fmaf(ssc, epx[(long)m * N + nn0 + j], vv);
                    vp[j] = vv;
                }
                *reinterpret_cast<float4*>(Co + (long)m * N + nn0) = v;
            }
        }
    }
}

// ======== pass A: per-partition partials (dt in smem only) ==============
__global__ __launch_bounds__(128) void scanA_k(
    const float* __restrict__ xc, const float* __restrict__ xdbl,
    const float* __restrict__ Alog0, const float* __restrict__ Alog1,
    const float* __restrict__ dtw0, const float* __restrict__ dtw1,
    const float* __restrict__ dtb0, const float* __restrict__ dtb1,
    float* __restrict__ hp, long sdir_bd, long sdir_xd) {
    __shared__ float x_s[32 * 65];
    __shared__ float dt_s[32 * 65];
    __shared__ float rT[64 * 20];
    __shared__ float bT[64 * 20];
    int zz = blockIdx.z;
    int dir = zz >> 4, part = zz & 15;
    xc += (long)dir * sdir_bd;
    xdbl += (long)dir * sdir_xd;
    const float* Alog = dir ? Alog1 : Alog0;
    const float* dtw = dir ? dtw1 : dtw0;
    const float* dtb = dir ? dtb1 : dtb0;
    int b = blockIdx.y, d0 = blockIdx.x << 5;
    int t = threadIdx.x, lane = t & 31, wp = t >> 5;
    int r_in = (wp << 3) + (lane >> 2), sg = lane & 3;

    float An[4];
#pragma unroll
    for (int j = 0; j < 4; j++)
        An[j] = -__expf(Alog[(d0 + r_in) * NS + sg * 4 + j]);
    bool fastok = true;
#pragma unroll
    for (int j = 0; j < 4; j++) {
        float nn = (float)(sg * 4 + j + 1);
        fastok = fastok && (fabsf(An[j] + nn) < 1e-4f * nn);
    }
    int fast = __syncthreads_and(fastok ? 1 : 0);

    float wreg[16];
#pragma unroll
    for (int k = 0; k < 16; k++) wreg[k] = dtw[(d0 + lane) * 16 + k];
    float dtbv = dtb[d0 + lane];

    long baseBD = ((long)b * DI + d0) * Ll;
    long baseXD = (long)b * NKP * Ll;
    int mask = dir ? (SCH - 1) : 0;
    float nbase = (float)(sg * 4 + 1);
    float h0 = 0.f, h1 = 0.f, h2 = 0.f, h3 = 0.f;
    float pa0 = 1.f, pa1 = 1.f, pa2 = 1.f, pa3 = 1.f;

    for (int cc = 0; cc < PLEN / SCH; cc++) {
        int c0 = dir ? (Ll - part * PLEN - (cc + 1) * SCH) : (part * PLEN + cc * SCH);
#pragma unroll 4
        for (int q = 0; q < 16; q++) {
            int idx = q * 128 + t;
            int r = idx >> 6, c = idx & 63;
            x_s[r * 65 + c] = xc[baseBD + (long)r * Ll + c0 + c];
        }
        {
            int l = t & 63, kh = t >> 6;
#pragma unroll
            for (int k2 = 0; k2 < 8; k2++) {
                int k = kh * 8 + k2;
                rT[l * 20 + k] = xdbl[baseXD + (long)k * Ll + c0 + l];
                bT[l * 20 + k] = xdbl[baseXD + (long)(16 + k) * Ll + c0 + l];
            }
        }
        __syncthreads();
#pragma unroll 2
        for (int ii = 0; ii < 16; ii++) {
            int i = wp * 16 + ii;
            float acc = dtbv;
#pragma unroll
            for (int k4 = 0; k4 < 4; k4++) {
                float4 rv = *reinterpret_cast<const float4*>(&rT[i * 20 + k4 * 4]);
                acc = fmaf(rv.x, wreg[k4 * 4 + 0], acc);
                acc = fmaf(rv.y, wreg[k4 * 4 + 1], acc);
                acc = fmaf(rv.z, wreg[k4 * 4 + 2], acc);
                acc = fmaf(rv.w, wreg[k4 * 4 + 3], acc);
            }
            dt_s[lane * 65 + i] = (acc > 20.f) ? acc : log1pf(__expf(acc));
        }
        __syncthreads();
        if (fast) {
#pragma unroll 4
            for (int s = 0; s < SCH; s++) {
                int i = s ^ mask;
                float dtv = dt_s[r_in * 65 + i];
                float wv = dtv * x_s[r_in * 65 + i];
                float e1 = __expf(-dtv);
                float ee0 = __expf(-dtv * nbase);
                float4 Bv = *reinterpret_cast<const float4*>(&bT[i * 20 + sg * 4]);
                float ee1 = ee0 * e1, ee2 = ee1 * e1, ee3 = ee2 * e1;
                h0 = fmaf(ee0, h0, wv * Bv.x);
                h1 = fmaf(ee1, h1, wv * Bv.y);
                h2 = fmaf(ee2, h2, wv * Bv.z);
                h3 = fmaf(ee3, h3, wv * Bv.w);
                pa0 *= ee0; pa1 *= ee1; pa2 *= ee2; pa3 *= ee3;
            }
        } else {
#pragma unroll 4
            for (int s = 0; s < SCH; s++) {
                int i = s ^ mask;
                float dtv = dt_s[r_in * 65 + i];
                float wv = dtv * x_s[r_in * 65 + i];
                float ee0 = __expf(dtv * An[0]);
                float ee1 = __expf(dtv * An[1]);
                float ee2 = __expf(dtv * An[2]);
                float ee3 = __expf(dtv * An[3]);
                float4 Bv = *reinterpret_cast<const float4*>(&bT[i * 20 + sg * 4]);
                h0 = fmaf(ee0, h0, wv * Bv.x);
                h1 = fmaf(ee1, h1, wv * Bv.y);
                h2 = fmaf(ee2, h2, wv * Bv.z);
                h3 = fmaf(ee3, h3, wv * Bv.w);
                pa0 *= ee0; pa1 *= ee1; pa2 *= ee2; pa3 *= ee3;
            }
        }
        __syncthreads();
    }
    long hb = ((((long)(dir * 8 + b) * NPART + part) * DI) + d0 + r_in) * NS + sg * 4;
    hp[(hb + 0) * 2 + 0] = pa0; hp[(hb + 0) * 2 + 1] = h0;
    hp[(hb + 1) * 2 + 0] = pa1; hp[(hb + 1) * 2 + 1] = h1;
    hp[(hb + 2) * 2 + 0] = pa2; hp[(hb + 2) * 2 + 1] = h2;
    hp[(hb + 3) * 2 + 0] = pa3; hp[(hb + 3) * 2 + 1] = h3;
}

// ======== fixup: chain partition states =================================
__global__ void fixup_k(const float* __restrict__ hp, float* __restrict__ h0g) {
    int idx = blockIdx.x * 256 + threadIdx.x;  // 131072 total
    int dn = idx & 8191;
    int bb = (idx >> 13) & 7;
    int dir = idx >> 16;
    const long stride = (long)DI * NS;
    long base = ((long)(dir * 8 + bb) * NPART) * stride + dn;
    float carry = 0.f;
#pragma unroll
    for (int p = 0; p < NPART; p++) {
        long o = base + (long)p * stride;
        h0g[o] = carry;
        carry = fmaf(hp[o * 2], carry, hp[o * 2 + 1]);
    }
}

// ======== pass C: final scan, exact h0, dt recomputed, both dirs ========
__global__ __launch_bounds__(128) void scanC_k(
    const float* __restrict__ xc, const float* __restrict__ xdbl,
    const float* __restrict__ xz, const float* __restrict__ h0g,
    const float* __restrict__ Alog0, const float* __restrict__ Alog1,
    const float* __restrict__ Dp0, const float* __restrict__ Dp1,
    const float* __restrict__ dtw0, const float* __restrict__ dtw1,
    const float* __restrict__ dtb0, const float* __restrict__ dtb1,
    float* __restrict__ yT, long sdir_bd, long sdir_xd) {
    __shared__ float x_s[32 * 65];
    __shared__ float z_s[32 * 65];
    __shared__ float dt_s[32 * 65];
    __shared__ float yrT[32 * 65];   // union: rT (dt phase) / y_s (scan phase)
    __shared__ float bT[64 * 20];
    __shared__ float cT[64 * 20];
    __shared__ float sDp[32];
    float* rT = yrT;
    float* y_s = yrT;
    int zz = blockIdx.z;
    int dir = zz >> 4, part = zz & 15;
    xc += (long)dir * sdir_bd;
    yT += (long)dir * sdir_bd;
    xdbl += (long)dir * sdir_xd;
    const float* Alog = dir ? Alog1 : Alog0;
    const float* Dp = dir ? Dp1 : Dp0;
    const float* dtw = dir ? dtw1 : dtw0;
    const float* dtb = dir ? dtb1 : dtb0;
    int b = blockIdx.y, d0 = blockIdx.x << 5;
    int t = threadIdx.x, lane = t & 31, wp = t >> 5;
    int r_in = (wp << 3) + (lane >> 2), sg = lane & 3;

    float An[4];
#pragma unroll
    for (int j = 0; j < 4; j++)
        An[j] = -__expf(Alog[(d0 + r_in) * NS + sg * 4 + j]);
    bool fastok = true;
#pragma unroll
    for (int j = 0; j < 4; j++) {
        float nn = (float)(sg * 4 + j + 1);
        fastok = fastok && (fabsf(An[j] + nn) < 1e-4f * nn);
    }
    int fast = __syncthreads_and(fastok ? 1 : 0);
    if (t < 32) sDp[t] = Dp[d0 + t];

    float wreg[16];
#pragma unroll
    for (int k = 0; k < 16; k++) wreg[k] = dtw[(d0 + lane) * 16 + k];
    float dtbv = dtb[d0 + lane];

    long hb = (((long)(dir * 8 + b) * NPART + part) * DI + d0 + r_in) * NS + sg * 4;
    float h0 = h0g[hb + 0], h1 = h0g[hb + 1], h2 = h0g[hb + 2], h3 = h0g[hb + 3];

    long baseBD = ((long)b * DI + d0) * Ll;
    long baseXD = (long)b * NKP * Ll;
    long baseZ = ((long)b * E2 + DI + d0) * Ll;
    int mask = dir ? (SCH - 1) : 0;
    float nbase = (float)(sg * 4 + 1);

    for (int cc = 0; cc < PLEN / SCH; cc++) {
        int c0 = dir ? (Ll - part * PLEN - (cc + 1) * SCH) : (part * PLEN + cc * SCH);
#pragma unroll 4
        for (int q = 0; q < 16; q++) {
            int idx = q * 128 + t;
            int r = idx >> 6, c = idx & 63;
            long off = (long)r * Ll + c0 + c;
            x_s[r * 65 + c] = xc[baseBD + off];
            z_s[r * 65 + c] = xz[baseZ + off];
        }
        {
            int l = t & 63, kh = t >> 6;
#pragma unroll
            for (int k2 = 0; k2 < 8; k2++) {
                int k = kh * 8 + k2;
                rT[l * 20 + k] = xdbl[baseXD + (long)k * Ll + c0 + l];
                bT[l * 20 + k] = xdbl[baseXD + (long)(16 + k) * Ll + c0 + l];
                cT[l * 20 + k] = xdbl[baseXD + (long)(32 + k) * Ll + c0 + l];
            }
        }
        __syncthreads();
        // dt = softplus(rank . dtw + b) -> dt_s
#pragma unroll 2
        for (int ii = 0; ii < 16; ii++) {
            int i = wp * 16 + ii;
            float acc = dtbv;
#pragma unroll
            for (int k4 = 0; k4 < 4; k4++) {
                float4 rv = *reinterpret_cast<const float4*>(&rT[i * 20 + k4 * 4]);
                acc = fmaf(rv.x, wreg[k4 * 4 + 0], acc);
                acc = fmaf(rv.y, wreg[k4 * 4 + 1], acc);
                acc = fmaf(rv.z, wreg[k4 * 4 + 2], acc);
                acc = fmaf(rv.w, wreg[k4 * 4 + 3], acc);
            }
            dt_s[lane * 65 + i] = (acc > 20.f) ? acc : log1pf(__expf(acc));
        }
        __syncthreads();   // rT dead beyond here; y_s may overwrite
        if (fast) {
#pragma unroll 4
            for (int s = 0; s < SCH; s++) {
                int i = s ^ mask;
                float dtv = dt_s[r_in * 65 + i];
                float wv = dtv * x_s[r_in * 65 + i];
                float e1 = __expf(-dtv);
                float ee0 = __expf(-dtv * nbase);
                float4 Bv = *reinterpret_cast<const float4*>(&bT[i * 20 + sg * 4]);
                float4 Cv = *reinterpret_cast<const float4*>(&cT[i * 20 + sg * 4]);
                float ee1 = ee0 * e1, ee2 = ee1 * e1, ee3 = ee2 * e1;
                h0 = fmaf(ee0, h0, wv * Bv.x);
                h1 = fmaf(ee1, h1, wv * Bv.y);
                h2 = fmaf(ee2, h2, wv * Bv.z);
                h3 = fmaf(ee3, h3, wv * Bv.w);
                float p = h0 * Cv.x;
                p = fmaf(h1, Cv.y, p);
                p = fmaf(h2, Cv.z, p);
                p = fmaf(h3, Cv.w, p);
                p += __shfl_xor_sync(0xffffffffu, p, 1);
                p += __shfl_xor_sync(0xffffffffu, p, 2);
                if (sg == 0) y_s[r_in * 65 + i] = p;
            }
        } else {
#pragma unroll 4
            for (int s = 0; s < SCH; s++) {
                int i = s ^ mask;
                float dtv = dt_s[r_in * 65 + i];
                float wv = dtv * x_s[r_in * 65 + i];
                float ee0 = __expf(dtv * An[0]);
                float ee1 = __expf(dtv * An[1]);
                float ee2 = __expf(dtv * An[2]);
                float ee3 = __expf(dtv * An[3]);
                float4 Bv = *reinterpret_cast<const float4*>(&bT[i * 20 + sg * 4]);
                float4 Cv = *reinterpret_cast<const float4*>(&cT[i * 20 + sg * 4]);
                h0 = fmaf(ee0, h0, wv * Bv.x);
                h1 = fmaf(ee1, h1, wv * Bv.y);
                h2 = fmaf(ee2, h2, wv * Bv.z);
                h3 = fmaf(ee3, h3, wv * Bv.w);
                float p = h0 * Cv.x;
                p = fmaf(h1, Cv.y, p);
                p = fmaf(h2, Cv.z, p);
                p = fmaf(h3, Cv.w, p);
                p += __shfl_xor_sync(0xffffffffu, p, 1);
                p += __shfl_xor_sync(0xffffffffu, p, 2);
                if (sg == 0) y_s[r_in * 65 + i] = p;
            }
        }
        __syncthreads();
        float dpv = sDp[lane];
#pragma unroll 4
        for (int j = 0; j < 16; j++) {
            int l = wp * 16 + j;
            int off = lane * 65 + l;
            float yv = y_s[off] + dpv * x_s[off];
            float out = yv * siluf(z_s[off]);
            yT[((long)b * Ll + c0 + l) * DI + d0 + lane] = out;
        }
        __syncthreads();
    }
}

// ---------------- host launcher ----------------------------------------
extern "C" void kernel_launch(void* const* d_in, const int* in_sizes, int n_in,
                              void* d_out, int out_size) {
    const float* x = (const float*)d_in[0];
    const float* norm_g = (const float*)d_in[1];
    const float* norm_b = (const float*)d_in[2];
    const float* skip_s = (const float*)d_in[3];
    const float* proj_w = (const float*)d_in[4];
    const float* proj_b = (const float*)d_in[5];
    const float* in_proj_w = (const float*)d_in[6];
    const float* out_proj_w = (const float*)d_in[7];
    const float* conv_w[2] = {(const float*)d_in[8], (const float*)d_in[15]};
    const float* conv_b[2] = {(const float*)d_in[9], (const float*)d_in[16]};
    const float* x_proj_w[2] = {(const float*)d_in[10], (const float*)d_in[17]};
    const float* dt_w[2] = {(const float*)d_in[11], (const float*)d_in[18]};
    const float* dt_bv[2] = {(const float*)d_in[12], (const float*)d_in[19]};
    const float* A_logv[2] = {(const float*)d_in[13], (const float*)d_in[20]};
    const float* Dpv[2] = {(const float*)d_in[14], (const float*)d_in[21]};

    __nv_bfloat16 *xnh, *xnl, *xmh, *xml;
    __nv_bfloat16 *wih, *wil, *woh, *wol, *wph, *wpl;
    float *xt, *xz, *xcbuf, *xdblbuf, *ybuf, *xm, *hpbuf, *h0buf;
    cudaGetSymbolAddress((void**)&xnh, g_xnh);
    cudaGetSymbolAddress((void**)&xnl, g_xnl);
    cudaGetSymbolAddress((void**)&xt, g_xt);
    cudaGetSymbolAddress((void**)&xz, g_xz);
    cudaGetSymbolAddress((void**)&xcbuf, g_xc);
    cudaGetSymbolAddress((void**)&xdblbuf, g_xdbl);
    cudaGetSymbolAddress((void**)&ybuf, g_y);
    cudaGetSymbolAddress((void**)&hpbuf, g_hp);
    cudaGetSymbolAddress((void**)&h0buf, g_h0);
    cudaGetSymbolAddress((void**)&xm, g_xm);
    cudaGetSymbolAddress((void**)&xmh, g_xmh);
    cudaGetSymbolAddress((void**)&xml, g_xml);
    cudaGetSymbolAddress((void**)&wih, g_wih);
    cudaGetSymbolAddress((void**)&wil, g_wil);
    cudaGetSymbolAddress((void**)&woh, g_woh);
    cudaGetSymbolAddress((void**)&wol, g_wol);
    cudaGetSymbolAddress((void**)&wph, g_wph);
    cudaGetSymbolAddress((void**)&wpl, g_wpl);
    const long SBD = (long)Bb * DI * Ll;
    const long SXD = (long)Bb * NKP * Ll;

    const int M = Bb * Ll;  // 32768
    const int TCSM = 128 * 132 * 4;  // 67584 (>= 2x32768 stages)

    cudaFuncSetAttribute(tc_gemm<true, 0, false>, cudaFuncAttributeMaxDynamicSharedMemorySize, TCSM);
    cudaFuncSetAttribute(tc_gemm<false, 3, true>, cudaFuncAttributeMaxDynamicSharedMemorySize, TCSM);
    cudaFuncSetAttribute(tc_gemm<true, 2, false>, cudaFuncAttributeMaxDynamicSharedMemorySize, TCSM);

    wsplit_k<<<(E2 * Cc + 255) / 256, 256>>>(in_proj_w, wih, wil, E2 * Cc);   // 0
    ln1_k<<<dim3(Ll / 32, Bb), 256>>>(x, norm_g, norm_b, xnh, xnl, xt);       // 1
    tc_gemm<true, 0, false><<<dim3(M / 128, E2 / 128), 256, TCSM>>>(          // 2 in_proj
        xnh, xnl, wih, wil, nullptr, nullptr,
        xz, E2, Cc, nullptr, nullptr, nullptr);
    conv_silu_k<<<dim3(DI, Bb), 256>>>(                                       // 3 (profiled)
        xz, conv_w[0], conv_b[0], conv_w[1], conv_b[1], xcbuf, xcbuf + SBD);
    gemm_k<true, true, 0, 128, 64, false><<<dim3(M / 128, 1, 2), 256>>>(      // 4 x_proj
        xcbuf, nullptr, x_proj_w[0], x_proj_w[1], xdblbuf, NKP, DI,
        (long)DI * Ll, (long)Ll, SBD, SXD, nullptr, nullptr, nullptr, nullptr);
    scanA_k<<<dim3(DI / 32, Bb, 2 * NPART), 128>>>(                           // 5
        xcbuf, xdblbuf, A_logv[0], A_logv[1], dt_w[0], dt_w[1],
        dt_bv[0], dt_bv[1], hpbuf, SBD, SXD);
    fixup_k<<<512, 256>>>(hpbuf, h0buf);                                      // 6
    scanC_k<<<dim3(DI / 32, Bb, 2 * NPART), 128>>>(                           // 7
        xcbuf, xdblbuf, xz, h0buf, A_logv[0], A_logv[1], Dpv[0], Dpv[1],
        dt_w[0], dt_w[1], dt_bv[0], dt_bv[1], ybuf, SBD, SXD);
    wsplit_k<<<(Cc * DI + 255) / 256, 256>>>(out_proj_w, woh, wol, Cc * DI);  // 8
    tc_gemm<false, 3, true><<<dim3(M / 128, Cc / 128), 256, TCSM>>>(          // 9 out_proj
        nullptr, nullptr, woh, wol, ybuf, ybuf + SBD,
        xm, Cc, DI, nullptr, xt, skip_s);
    ln2_k<<<M, 256>>>(xm, norm_g, norm_b, xmh, xml);                          // 10
    wsplit_k<<<(Cc * Cc + 255) / 256, 256>>>(proj_w, wph, wpl, Cc * Cc);      // 11
    tc_gemm<true, 2, false><<<dim3(M / 128, Cc / 128), 256, TCSM>>>(          // 12 proj
        xmh, xml, wph, wpl, nullptr, nullptr,
        (float*)d_out, Cc, Cc, proj_b, nullptr, nullptr);
}

// round 16
// speedup vs baseline: 1.0652x; 1.0652x over previous
#include <cuda_runtime.h>
#include <cuda_bf16.h>
#include <math.h>
#include <stdint.h>

#define Bb 8
#define Ll 4096
#define Cc 256
#define E2 1024
#define DI 512
#define NKP 48   // DT_RANK + 2*D_STATE
#define NS 16    // D_STATE
#define NPART 16
#define PLEN 256
#define SCH 64

// ---------------- scratch (static device allocations) ----------------
__device__ __nv_bfloat16 g_xnh[Bb * Ll * Cc];
__device__ __nv_bfloat16 g_xnl[Bb * Ll * Cc];
__device__ float g_xt[Bb * Ll * Cc];
__device__ float g_xz[Bb * E2 * Ll];
__device__ float g_xc[2][Bb * DI * Ll];           // conv+silu out per dir (b,d,l)
__device__ float g_xdbl[2][Bb * NKP * Ll];
__device__ float g_dtg[2][Bb * DI * Ll];
__device__ float g_y[2][Bb * Ll * DI];            // scan out transposed (b,l,d)
__device__ float g_hp[2 * Bb * NPART * DI * NS * 2];
__device__ float g_h0[2 * Bb * NPART * DI * NS];
__device__ __nv_bfloat16 g_yth[Bb * Ll * DI];
__device__ __nv_bfloat16 g_ytl[Bb * Ll * DI];
__device__ float g_xm[Bb * Ll * Cc];
__device__ __nv_bfloat16 g_xmh[Bb * Ll * Cc];
__device__ __nv_bfloat16 g_xml[Bb * Ll * Cc];
__device__ __nv_bfloat16 g_wih[E2 * Cc], g_wil[E2 * Cc];
__device__ __nv_bfloat16 g_woh[Cc * DI], g_wol[Cc * DI];
__device__ __nv_bfloat16 g_wph[Cc * Cc], g_wpl[Cc * Cc];
__device__ __nv_bfloat16 g_wxh[2 * NKP * DI], g_wxl[2 * NKP * DI];

__device__ __forceinline__ float siluf(float v) {
    return v / (1.f + __expf(-v));
}

__device__ __forceinline__ uint32_t smem_u32(const void* p) {
    uint32_t a;
    asm("{ .reg .u64 t; cvta.to.shared.u64 t, %1; cvt.u32.u64 %0, t; }"
        : "=r"(a) : "l"(p));
    return a;
}

#define CPA16(dst, src) \
    asm volatile("cp.async.cg.shared.global [%0], [%1], 16;" :: "r"(dst), "l"(src))
#define CPA_COMMIT() asm volatile("cp.async.commit_group;" ::: "memory")
#define CPA_WAIT1() asm volatile("cp.async.wait_group 1;" ::: "memory")
#define CPA_WAIT0() asm volatile("cp.async.wait_group 0;" ::: "memory")

#define LDSM4(r, addr) \
    asm volatile("ldmatrix.sync.aligned.m8n8.x4.shared.b16 {%0,%1,%2,%3}, [%4];" \
        : "=r"((r)[0]), "=r"((r)[1]), "=r"((r)[2]), "=r"((r)[3]) : "r"(addr))

#define MMA16816(c, a, b0, b1) \
    asm volatile("mma.sync.aligned.m16n8k16.row.col.f32.bf16.bf16.f32 " \
        "{%0,%1,%2,%3},{%4,%5,%6,%7},{%8,%9},{%0,%1,%2,%3};" \
        : "+f"((c)[0]), "+f"((c)[1]), "+f"((c)[2]), "+f"((c)[3]) \
        : "r"((a)[0]), "r"((a)[1]), "r"((a)[2]), "r"((a)[3]), "r"(b0), "r"(b1))

// ---------------- weight fp32 -> bf16 hi/lo split ------------------------
__global__ void wsplit_k(const float* __restrict__ w, __nv_bfloat16* __restrict__ h,
                         __nv_bfloat16* __restrict__ l, int n) {
    int i = blockIdx.x * 256 + threadIdx.x;
    if (i < n) {
        float v = w[i];
        __nv_bfloat16 hh = __float2bfloat16(v);
        h[i] = hh;
        l[i] = __float2bfloat16(v - __bfloat162float(hh));
    }
}

// ---------------- LayerNorm 1 ------------------------------------------
__global__ void ln1_k(const float* __restrict__ x, const float* __restrict__ g,
                      const float* __restrict__ bta, __nv_bfloat16* __restrict__ xnh,
                      __nv_bfloat16* __restrict__ xnl, float* __restrict__ xt) {
    __shared__ float tile[256][33];
    __shared__ float red1[8][33];
    __shared__ float red2[8][33];
    __shared__ float smean[32], srstd[32];
    int b = blockIdx.y;
    int l0 = blockIdx.x << 5;
    int t = threadIdx.x;
    int lx = t & 31, cy = t >> 5;
    long base = (long)b * Cc * Ll + l0;
    float s = 0.f, sq = 0.f;
#pragma unroll
    for (int q = 0; q < 32; q++) {
        int c = (cy << 5) + q;
        float v = x[base + (long)c * Ll + lx];
        tile[c][lx] = v;
        s += v;
        sq += v * v;
    }
    red1[cy][lx] = s;
    red2[cy][lx] = sq;
    __syncthreads();
    if (t < 32) {
        float ts = 0.f, tq = 0.f;
#pragma unroll
        for (int p = 0; p < 8; p++) { ts += red1[p][t]; tq += red2[p][t]; }
        float mean = ts * (1.f / 256.f);
        float var = tq * (1.f / 256.f) - mean * mean;
        smean[t] = mean;
        srstd[t] = rsqrtf(var + 1e-5f);
    }
    __syncthreads();
    float gv = g[t], bv = bta[t];
#pragma unroll
    for (int li = 0; li < 32; li++) {
        float raw = tile[t][li];
        long o = ((long)b * Ll + l0 + li) * Cc + t;
        xt[o] = raw;
        float vn = (raw - smean[li]) * srstd[li] * gv + bv;
        __nv_bfloat16 h = __float2bfloat16(vn);
        xnh[o] = h;
        xnl[o] = __float2bfloat16(vn - __bfloat162float(h));
    }
}

// ---------------- LayerNorm 2 ------------------------------------------
__global__ void ln2_k(const float* __restrict__ xm, const float* __restrict__ g,
                      const float* __restrict__ bta, __nv_bfloat16* __restrict__ oh,
                      __nv_bfloat16* __restrict__ ol) {
    int row = blockIdx.x, t = threadIdx.x;
    long o = (long)row * Cc + t;
    float v = xm[o];
    float s = v, sq = v * v;
#pragma unroll
    for (int off = 16; off; off >>= 1) {
        s += __shfl_xor_sync(0xffffffffu, s, off);
        sq += __shfl_xor_sync(0xffffffffu, sq, off);
    }
    __shared__ float as_[8], aq_[8];
    if ((t & 31) == 0) { as_[t >> 5] = s; aq_[t >> 5] = sq; }
    __syncthreads();
    float ts = 0.f, tq = 0.f;
#pragma unroll
    for (int p = 0; p < 8; p++) { ts += as_[p]; tq += aq_[p]; }
    float mean = ts * (1.f / 256.f);
    float rs = rsqrtf(tq * (1.f / 256.f) - mean * mean + 1e-5f);
    float vn = (v - mean) * rs * g[t] + bta[t];
    __nv_bfloat16 h = __float2bfloat16(vn);
    oh[o] = h;
    ol[o] = __float2bfloat16(vn - __bfloat162float(h));
}

// ---------------- conv+silu: one (b,d) row per block (33us) -------------
__global__ __launch_bounds__(256) void conv_silu_k(
    const float* __restrict__ xz,
    const float* __restrict__ cwf, const float* __restrict__ cbf,
    const float* __restrict__ cwr, const float* __restrict__ cbr,
    float* __restrict__ xcf, float* __restrict__ xcr) {
    __shared__ float row[Ll];
    int d = blockIdx.x, b = blockIdx.y;
    int t = threadIdx.x;
    const float* xi = xz + ((long)b * E2 + d) * Ll;
#pragma unroll
    for (int q = 0; q < 4; q++) {
        int f = q * 256 + t;
        *reinterpret_cast<float4*>(&row[f * 4]) =
            *reinterpret_cast<const float4*>(&xi[f * 4]);
    }
    float wf0 = cwf[d * 4 + 0], wf1 = cwf[d * 4 + 1], wf2 = cwf[d * 4 + 2], wf3 = cwf[d * 4 + 3];
    float wr0 = cwr[d * 4 + 0], wr1 = cwr[d * 4 + 1], wr2 = cwr[d * 4 + 2], wr3 = cwr[d * 4 + 3];
    float bf = cbf[d], br = cbr[d];
    __syncthreads();
    long ob = ((long)b * DI + d) * Ll;
#pragma unroll
    for (int q = 0; q < 4; q++) {
        int l0 = (q * 256 + t) * 4;
        float4 of, orv;
        float* ofp = &of.x;
        float* orp = &orv.x;
#pragma unroll
        for (int u = 0; u < 4; u++) {
            int l = l0 + u;
            float sf = bf + wf3 * row[l];
            if (l - 3 >= 0) sf += wf0 * row[l - 3];
            if (l - 2 >= 0) sf += wf1 * row[l - 2];
            if (l - 1 >= 0) sf += wf2 * row[l - 1];
            ofp[u] = siluf(sf);
            float sr = br + wr3 * row[l];
            if (l + 3 < Ll) sr += wr0 * row[l + 3];
            if (l + 2 < Ll) sr += wr1 * row[l + 2];
            if (l + 1 < Ll) sr += wr2 * row[l + 1];
            orp[u] = siluf(sr);
        }
        *reinterpret_cast<float4*>(&xcf[ob + l0]) = of;
        *reinterpret_cast<float4*>(&xcr[ob + l0]) = orv;
    }
}

// ======= mma.sync split-bf16 GEMM, 2-stage pipeline =====================
// OUTT: C at (m/L)*(N*L)+n*L+(m%L), guarded for N<128; else row-major.
// EPI: 0 none | 2 +epv[n] | 3 + eps[0]*epx[m*N+n]
// DIRB: blockIdx.z = dir (A/Acol offset sAd, C offset sCd, W -> Wh1/Wl1)
// CMA: A built from fp32 column-major Acol (b,k-major,l), split in-flight.
template <bool OUTT, int EPI, bool DIRB, bool CMA>
__global__ __launch_bounds__(256) void tc_gemm(
    const __nv_bfloat16* __restrict__ Ah, const __nv_bfloat16* __restrict__ Al,
    const __nv_bfloat16* __restrict__ Wh, const __nv_bfloat16* __restrict__ Wl,
    const __nv_bfloat16* __restrict__ Wh1, const __nv_bfloat16* __restrict__ Wl1,
    const float* __restrict__ Acol,
    float* __restrict__ Co, int N, int K, long sAd, long sCd,
    const float* __restrict__ epv, const float* __restrict__ epx,
    const float* __restrict__ eps) {
    extern __shared__ __align__(16) char smraw[];
    float* Cs = (float*)smraw;
    int t = threadIdx.x;
    int lane = t & 31, wid = t >> 5;
    int wm = wid >> 2, wn = wid & 3;
    int m0 = blockIdx.x * 128, n0 = blockIdx.y * 128;
    if (DIRB) {
        int dir = blockIdx.z;
        if (CMA) Acol += (long)dir * sAd;
        else { Ah += (long)dir * sAd; Al += (long)dir * sAd; }
        if (dir) { Wh = Wh1; Wl = Wl1; }
        Co += (long)dir * sCd;
    }
    const float* acbase = CMA ? (Acol + (long)(m0 / Ll) * DI * Ll + (m0 % Ll))
                              : nullptr;
    uint32_t sbase = smem_u32(smraw);

    auto ldst = [&](int stage, int k0) {
#pragma unroll
        for (int q = 0; q < 2; q++) {
            int unit = t + q * 256;
            int r = unit >> 2, c = unit & 3;
            uint32_t d = sbase + stage * 32768 + r * 64 + 16 * (c ^ ((r >> 1) & 3));
            long goff = (long)r * K + k0 + c * 8;
            if (n0 + r < N) {
                CPA16(d + 16384, Wh + (long)n0 * K + goff);
                CPA16(d + 24576, Wl + (long)n0 * K + goff);
            } else {
                uint4 z = make_uint4(0, 0, 0, 0);
                *reinterpret_cast<uint4*>(smraw + stage * 32768 + r * 64 +
                                          16 * (c ^ ((r >> 1) & 3)) + 16384) = z;
                *reinterpret_cast<uint4*>(smraw + stage * 32768 + r * 64 +
                                          16 * (c ^ ((r >> 1) & 3)) + 24576) = z;
            }
            if (!CMA) {
                CPA16(d, Ah + (long)m0 * K + goff);
                CPA16(d + 8192, Al + (long)m0 * K + goff);
            }
        }
        CPA_COMMIT();
        if (CMA) {
#pragma unroll
            for (int q = 0; q < 2; q++) {
                int unit = t + q * 256;
                int k = unit & 31, mg = unit >> 5;
                const float* src = acbase + (long)(k0 + k) * Ll + mg * 8;
                float4 v0 = *reinterpret_cast<const float4*>(src);
                float4 v1 = *reinterpret_cast<const float4*>(src + 4);
                float vv[8] = {v0.x, v0.y, v0.z, v0.w, v1.x, v1.y, v1.z, v1.w};
                int kc = k >> 3, kb = (k & 7) * 2;
#pragma unroll
                for (int j = 0; j < 8; j++) {
                    int m = mg * 8 + j;
                    int off = stage * 32768 + m * 64 + 16 * (kc ^ ((m >> 1) & 3)) + kb;
                    __nv_bfloat16 h = __float2bfloat16(vv[j]);
                    *reinterpret_cast<__nv_bfloat16*>(smraw + off) = h;
                    *reinterpret_cast<__nv_bfloat16*>(smraw + off + 8192) =
                        __float2bfloat16(vv[j] - __bfloat162float(h));
                }
            }
        }
    };

    float acc[4][4][4];
#pragma unroll
    for (int i = 0; i < 4; i++)
#pragma unroll
        for (int j = 0; j < 4; j++)
#pragma unroll
            for (int q = 0; q < 4; q++) acc[i][j][q] = 0.f;

    int NC = K >> 5;
    ldst(0, 0);
    int row_l = (lane & 7) + ((lane >> 3) & 1) * 8;
    int khalf = (lane >> 4) & 1;
    for (int it = 0; it < NC; it++) {
        if (it + 1 < NC) { ldst((it + 1) & 1, (it + 1) << 5); CPA_WAIT1(); }
        else CPA_WAIT0();
        __syncthreads();
        uint32_t abase = sbase + (it & 1) * 32768;
#pragma unroll
        for (int kk = 0; kk < 2; kk++) {
            uint32_t ah[4][4], al[4][4];
#pragma unroll
            for (int mt = 0; mt < 4; mt++) {
                int r = wm * 64 + mt * 16 + row_l;
                uint32_t ad = abase + r * 64 + 16 * ((kk * 2 + khalf) ^ ((r >> 1) & 3));
                LDSM4(ah[mt], ad);
                LDSM4(al[mt], ad + 8192);
            }
            uint32_t bh[4][2], bl[4][2];
#pragma unroll
            for (int np = 0; np < 2; np++) {
                int r = wn * 32 + np * 16 + row_l;
                uint32_t bd = abase + 16384 + r * 64 + 16 * ((kk * 2 + khalf) ^ ((r >> 1) & 3));
                uint32_t tmp[4];
                LDSM4(tmp, bd);
                bh[np * 2][0] = tmp[0]; bh[np * 2][1] = tmp[2];
                bh[np * 2 + 1][0] = tmp[1]; bh[np * 2 + 1][1] = tmp[3];
                LDSM4(tmp, bd + 8192);
                bl[np * 2][0] = tmp[0]; bl[np * 2][1] = tmp[2];
                bl[np * 2 + 1][0] = tmp[1]; bl[np * 2 + 1][1] = tmp[3];
            }
#pragma unroll
            for (int mt = 0; mt < 4; mt++)
#pragma unroll
                for (int nt = 0; nt < 4; nt++) {
                    MMA16816(acc[mt][nt], ah[mt], bh[nt][0], bh[nt][1]);
                    MMA16816(acc[mt][nt], ah[mt], bl[nt][0], bl[nt][1]);
                    MMA16816(acc[mt][nt], al[mt], bh[nt][0], bh[nt][1]);
                }
        }
        __syncthreads();
    }

#pragma unroll
    for (int mt = 0; mt < 4; mt++) {
        int m = wm * 64 + mt * 16 + (lane >> 2);
#pragma unroll
        for (int nt = 0; nt < 4; nt++) {
            int n = wn * 32 + nt * 8 + (lane & 3) * 2;
            Cs[n * 132 + m] = acc[mt][nt][0];
            Cs[(n + 1) * 132 + m] = acc[mt][nt][1];
            Cs[n * 132 + m + 8] = acc[mt][nt][2];
            Cs[(n + 1) * 132 + m + 8] = acc[mt][nt][3];
        }
    }
    __syncthreads();

    if (OUTT) {
        long bO = (long)(m0 / Ll) * ((long)N * Ll) + (m0 % Ll);
#pragma unroll
        for (int q = 0; q < 16; q++) {
            int nr = (t >> 5) + q * 8;
            int mc = lane * 4;
            int nn = n0 + nr;
            if (nn < N) {
                float4 v = *reinterpret_cast<const float4*>(&Cs[nr * 132 + mc]);
                if (EPI == 2) {
                    float bv = epv[nn];
                    v.x += bv; v.y += bv; v.z += bv; v.w += bv;
                }
                *reinterpret_cast<float4*>(Co + bO + (long)nn * Ll + mc) = v;
            }
        }
    } else {
        float ss = (EPI == 3) ? eps[0] : 0.f;
        int row = t >> 1, ch2 = (t & 1) * 64;
#pragma unroll
        for (int f = 0; f < 16; f++) {
            int c = ch2 + f * 4;
            float4 v;
            v.x = Cs[(c + 0) * 132 + row];
            v.y = Cs[(c + 1) * 132 + row];
            v.z = Cs[(c + 2) * 132 + row];
            v.w = Cs[(c + 3) * 132 + row];
            long go = (long)(m0 + row) * N + n0 + c;
            if (EPI == 3) {
                float4 sk = *reinterpret_cast<const float4*>(epx + go);
                v.x = fmaf(ss, sk.x, v.x); v.y = fmaf(ss, sk.y, v.y);
                v.z = fmaf(ss, sk.z, v.z); v.w = fmaf(ss, sk.w, v.w);
            }
            *reinterpret_cast<float4*>(Co + go) = v;
        }
    }
}

// ======== pass A: per-partition partials (materializes dt) ==============
__global__ __launch_bounds__(128) void scanA_k(
    const float* __restrict__ xc, const float* __restrict__ xdbl,
    const float* __restrict__ Alog0, const float* __restrict__ Alog1,
    const float* __restrict__ dtw0, const float* __restrict__ dtw1,
    const float* __restrict__ dtb0, const float* __restrict__ dtb1,
    float* __restrict__ dtg, float* __restrict__ hp,
    long sdir_bd, long sdir_xd) {
    __shared__ float x_s[32 * 65];
    __shared__ float dt_s[32 * 65];
    __shared__ float rT[64 * 20];
    __shared__ float bT[64 * 20];
    int zz = blockIdx.z;
    int dir = zz >> 4, part = zz & 15;
    xc += (long)dir * sdir_bd;
    dtg += (long)dir * sdir_bd;
    xdbl += (long)dir * sdir_xd;
    const float* Alog = dir ? Alog1 : Alog0;
    const float* dtw = dir ? dtw1 : dtw0;
    const float* dtb = dir ? dtb1 : dtb0;
    int b = blockIdx.y, d0 = blockIdx.x << 5;
    int t = threadIdx.x, lane = t & 31, wp = t >> 5;
    int r_in = (wp << 3) + (lane >> 2), sg = lane & 3;

    float An[4];
#pragma unroll
    for (int j = 0; j < 4; j++)
        An[j] = -__expf(Alog[(d0 + r_in) * NS + sg * 4 + j]);
    bool fastok = true;
#pragma unroll
    for (int j = 0; j < 4; j++) {
        float nn = (float)(sg * 4 + j + 1);
        fastok = fastok && (fabsf(An[j] + nn) < 1e-4f * nn);
    }
    int fast = __syncthreads_and(fastok ? 1 : 0);

    float wreg[16];
#pragma unroll
    for (int k = 0; k < 16; k++) wreg[k] = dtw[(d0 + lane) * 16 + k];
    float dtbv = dtb[d0 + lane];

    long baseBD = ((long)b * DI + d0) * Ll;
    long baseXD = (long)b * NKP * Ll;
    int mask = dir ? (SCH - 1) : 0;
    float nbase = (float)(sg * 4 + 1);
    float h0 = 0.f, h1 = 0.f, h2 = 0.f, h3 = 0.f;
    float pa0 = 1.f, pa1 = 1.f, pa2 = 1.f, pa3 = 1.f;

    for (int cc = 0; cc < PLEN / SCH; cc++) {
        int c0 = dir ? (Ll - part * PLEN - (cc + 1) * SCH) : (part * PLEN + cc * SCH);
#pragma unroll 4
        for (int q = 0; q < 16; q++) {
            int idx = q * 128 + t;
            int r = idx >> 6, c = idx & 63;
            x_s[r * 65 + c] = xc[baseBD + (long)r * Ll + c0 + c];
        }
        {
            int l = t & 63, kh = t >> 6;
#pragma unroll
            for (int k2 = 0; k2 < 8; k2++) {
                int k = kh * 8 + k2;
                rT[l * 20 + k] = xdbl[baseXD + (long)k * Ll + c0 + l];
                bT[l * 20 + k] = xdbl[baseXD + (long)(16 + k) * Ll + c0 + l];
            }
        }
        __syncthreads();
#pragma unroll 2
        for (int ii = 0; ii < 16; ii++) {
            int i = wp * 16 + ii;
            float acc = dtbv;
#pragma unroll
            for (int k4 = 0; k4 < 4; k4++) {
                float4 rv = *reinterpret_cast<const float4*>(&rT[i * 20 + k4 * 4]);
                acc = fmaf(rv.x, wreg[k4 * 4 + 0], acc);
                acc = fmaf(rv.y, wreg[k4 * 4 + 1], acc);
                acc = fmaf(rv.z, wreg[k4 * 4 + 2], acc);
                acc = fmaf(rv.w, wreg[k4 * 4 + 3], acc);
            }
            dt_s[lane * 65 + i] = (acc > 20.f) ? acc : log1pf(__expf(acc));
        }
        __syncthreads();
#pragma unroll 4
        for (int q = 0; q < 16; q++) {
            int idx = q * 128 + t;
            int r = idx >> 6, c = idx & 63;
            dtg[baseBD + (long)r * Ll + c0 + c] = dt_s[r * 65 + c];
        }
        if (fast) {
#pragma unroll 4
            for (int s = 0; s < SCH; s++) {
                int i = s ^ mask;
                float dtv = dt_s[r_in * 65 + i];
                float wv = dtv * x_s[r_in * 65 + i];
                float e1 = __expf(-dtv);
                float ee0 = __expf(-dtv * nbase);
                float4 Bv = *reinterpret_cast<const float4*>(&bT[i * 20 + sg * 4]);
                float ee1 = ee0 * e1, ee2 = ee1 * e1, ee3 = ee2 * e1;
                h0 = fmaf(ee0, h0, wv * Bv.x);
                h1 = fmaf(ee1, h1, wv * Bv.y);
                h2 = fmaf(ee2, h2, wv * Bv.z);
                h3 = fmaf(ee3, h3, wv * Bv.w);
                pa0 *= ee0; pa1 *= ee1; pa2 *= ee2; pa3 *= ee3;
            }
        } else {
#pragma unroll 4
            for (int s = 0; s < SCH; s++) {
                int i = s ^ mask;
                float dtv = dt_s[r_in * 65 + i];
                float wv = dtv * x_s[r_in * 65 + i];
                float ee0 = __expf(dtv * An[0]);
                float ee1 = __expf(dtv * An[1]);
                float ee2 = __expf(dtv * An[2]);
                float ee3 = __expf(dtv * An[3]);
                float4 Bv = *reinterpret_cast<const float4*>(&bT[i * 20 + sg * 4]);
                h0 = fmaf(ee0, h0, wv * Bv.x);
                h1 = fmaf(ee1, h1, wv * Bv.y);
                h2 = fmaf(ee2, h2, wv * Bv.z);
                h3 = fmaf(ee3, h3, wv * Bv.w);
                pa0 *= ee0; pa1 *= ee1; pa2 *= ee2; pa3 *= ee3;
            }
        }
        __syncthreads();
    }
    long hb = ((((long)(dir * 8 + b) * NPART + part) * DI) + d0 + r_in) * NS + sg * 4;
    hp[(hb + 0) * 2 + 0] = pa0; hp[(hb + 0) * 2 + 1] = h0;
    hp[(hb + 1) * 2 + 0] = pa1; hp[(hb + 1) * 2 + 1] = h1;
    hp[(hb + 2) * 2 + 0] = pa2; hp[(hb + 2) * 2 + 1] = h2;
    hp[(hb + 3) * 2 + 0] = pa3; hp[(hb + 3) * 2 + 1] = h3;
}

// ======== fixup: chain partition states =================================
__global__ void fixup_k(const float* __restrict__ hp, float* __restrict__ h0g) {
    int idx = blockIdx.x * 256 + threadIdx.x;  // 131072 total
    int dn = idx & 8191;
    int bb = (idx >> 13) & 7;
    int dir = idx >> 16;
    const long stride = (long)DI * NS;
    long base = ((long)(dir * 8 + bb) * NPART) * stride + dn;
    float carry = 0.f;
#pragma unroll
    for (int p = 0; p < NPART; p++) {
        long o = base + (long)p * stride;
        h0g[o] = carry;
        carry = fmaf(hp[o * 2], carry, hp[o * 2 + 1]);
    }
}

// ======== pass C: final scan with exact h0, transposed gated out ========
__global__ __launch_bounds__(128) void scanC_k(
    const float* __restrict__ xc, const float* __restrict__ xdbl,
    const float* __restrict__ xz, const float* __restrict__ dtg,
    const float* __restrict__ h0g,
    const float* __restrict__ Alog0, const float* __restrict__ Alog1,
    const float* __restrict__ Dp0, const float* __restrict__ Dp1,
    float* __restrict__ yT, long sdir_bd, long sdir_xd) {
    __shared__ float x_s[32 * 65];
    __shared__ float z_s[32 * 65];
    __shared__ float dt_s[32 * 65];
    __shared__ float y_s[32 * 65];
    __shared__ float bT[64 * 20];
    __shared__ float cT[64 * 20];
    __shared__ float sDp[32];
    int zz = blockIdx.z;
    int dir = zz >> 4, part = zz & 15;
    xc += (long)dir * sdir_bd;
    dtg += (long)dir * sdir_bd;
    yT += (long)dir * sdir_bd;
    xdbl += (long)dir * sdir_xd;
    const float* Alog = dir ? Alog1 : Alog0;
    const float* Dp = dir ? Dp1 : Dp0;
    int b = blockIdx.y, d0 = blockIdx.x << 5;
    int t = threadIdx.x, lane = t & 31, wp = t >> 5;
    int r_in = (wp << 3) + (lane >> 2), sg = lane & 3;

    float An[4];
#pragma unroll
    for (int j = 0; j < 4; j++)
        An[j] = -__expf(Alog[(d0 + r_in) * NS + sg * 4 + j]);
    bool fastok = true;
#pragma unroll
    for (int j = 0; j < 4; j++) {
        float nn = (float)(sg * 4 + j + 1);
        fastok = fastok && (fabsf(An[j] + nn) < 1e-4f * nn);
    }
    int fast = __syncthreads_and(fastok ? 1 : 0);
    if (t < 32) sDp[t] = Dp[d0 + t];

    long hb = (((long)(dir * 8 + b) * NPART + part) * DI + d0 + r_in) * NS + sg * 4;
    float h0 = h0g[hb + 0], h1 = h0g[hb + 1], h2 = h0g[hb + 2], h3 = h0g[hb + 3];

    long baseBD = ((long)b * DI + d0) * Ll;
    long baseXD = (long)b * NKP * Ll;
    long baseZ = ((long)b * E2 + DI + d0) * Ll;
    int mask = dir ? (SCH - 1) : 0;
    float nbase = (float)(sg * 4 + 1);

    for (int cc = 0; cc < PLEN / SCH; cc++) {
        int c0 = dir ? (Ll - part * PLEN - (cc + 1) * SCH) : (part * PLEN + cc * SCH);
#pragma unroll 4
        for (int q = 0; q < 16; q++) {
            int idx = q * 128 + t;
            int r = idx >> 6, c = idx & 63;
            long off = (long)r * Ll + c0 + c;
            x_s[r * 65 + c] = xc[baseBD + off];
            z_s[r * 65 + c] = xz[baseZ + off];
            dt_s[r * 65 + c] = dtg[baseBD + off];
        }
        {
            int l = t & 63, kh = t >> 6;
#pragma unroll
            for (int k2 = 0; k2 < 8; k2++) {
                int k = kh * 8 + k2;
                bT[l * 20 + k] = xdbl[baseXD + (long)(16 + k) * Ll + c0 + l];
                cT[l * 20 + k] = xdbl[baseXD + (long)(32 + k) * Ll + c0 + l];
            }
        }
        __syncthreads();
        if (fast) {
#pragma unroll 4
            for (int s = 0; s < SCH; s++) {
                int i = s ^ mask;
                float dtv = dt_s[r_in * 65 + i];
                float wv = dtv * x_s[r_in * 65 + i];
                float e1 = __expf(-dtv);
                float ee0 = __expf(-dtv * nbase);
                float4 Bv = *reinterpret_cast<const float4*>(&bT[i * 20 + sg * 4]);
                float4 Cv = *reinterpret_cast<const float4*>(&cT[i * 20 + sg * 4]);
                float ee1 = ee0 * e1, ee2 = ee1 * e1, ee3 = ee2 * e1;
                h0 = fmaf(ee0, h0, wv * Bv.x);
                h1 = fmaf(ee1, h1, wv * Bv.y);
                h2 = fmaf(ee2, h2, wv * Bv.z);
                h3 = fmaf(ee3, h3, wv * Bv.w);
                float p = h0 * Cv.x;
                p = fmaf(h1, Cv.y, p);
                p = fmaf(h2, Cv.z, p);
                p = fmaf(h3, Cv.w, p);
                p += __shfl_xor_sync(0xffffffffu, p, 1);
                p += __shfl_xor_sync(0xffffffffu, p, 2);
                if (sg == 0) y_s[r_in * 65 + i] = p;
            }
        } else {
#pragma unroll 4
            for (int s = 0; s < SCH; s++) {
                int i = s ^ mask;
                float dtv = dt_s[r_in * 65 + i];
                float wv = dtv * x_s[r_in * 65 + i];
                float ee0 = __expf(dtv * An[0]);
                float ee1 = __expf(dtv * An[1]);
                float ee2 = __expf(dtv * An[2]);
                float ee3 = __expf(dtv * An[3]);
                float4 Bv = *reinterpret_cast<const float4*>(&bT[i * 20 + sg * 4]);
                float4 Cv = *reinterpret_cast<const float4*>(&cT[i * 20 + sg * 4]);
                h0 = fmaf(ee0, h0, wv * Bv.x);
                h1 = fmaf(ee1, h1, wv * Bv.y);
                h2 = fmaf(ee2, h2, wv * Bv.z);
                h3 = fmaf(ee3, h3, wv * Bv.w);
                float p = h0 * Cv.x;
                p = fmaf(h1, Cv.y, p);
                p = fmaf(h2, Cv.z, p);
                p = fmaf(h3, Cv.w, p);
                p += __shfl_xor_sync(0xffffffffu, p, 1);
                p += __shfl_xor_sync(0xffffffffu, p, 2);
                if (sg == 0) y_s[r_in * 65 + i] = p;
            }
        }
        __syncthreads();
        float dpv = sDp[lane];
#pragma unroll 4
        for (int j = 0; j < 16; j++) {
            int l = wp * 16 + j;
            int off = lane * 65 + l;
            float yv = y_s[off] + dpv * x_s[off];
            float out = yv * siluf(z_s[off]);
            yT[((long)b * Ll + c0 + l) * DI + d0 + lane] = out;
        }
        __syncthreads();
    }
}

// ---------------- yfuse: pure elementwise sum + bf16 split --------------
__global__ void yfuse_k(const float* __restrict__ y0, const float* __restrict__ y1,
                        __nv_bfloat16* __restrict__ yh, __nv_bfloat16* __restrict__ yl) {
    long i4 = (long)blockIdx.x * 256 + threadIdx.x;
    float4 a = reinterpret_cast<const float4*>(y0)[i4];
    float4 bb = reinterpret_cast<const float4*>(y1)[i4];
    float v0 = a.x + bb.x, v1 = a.y + bb.y, v2 = a.z + bb.z, v3 = a.w + bb.w;
    __nv_bfloat16 h0 = __float2bfloat16(v0), h1 = __float2bfloat16(v1);
    __nv_bfloat16 h2 = __float2bfloat16(v2), h3 = __float2bfloat16(v3);
    __nv_bfloat162 hh01 = __halves2bfloat162(h0, h1);
    __nv_bfloat162 hh23 = __halves2bfloat162(h2, h3);
    uint2 uh = make_uint2(*reinterpret_cast<uint32_t*>(&hh01),
                          *reinterpret_cast<uint32_t*>(&hh23));
    reinterpret_cast<uint2*>(yh)[i4] = uh;
    __nv_bfloat16 q0 = __float2bfloat16(v0 - __bfloat162float(h0));
    __nv_bfloat16 q1 = __float2bfloat16(v1 - __bfloat162float(h1));
    __nv_bfloat16 q2 = __float2bfloat16(v2 - __bfloat162float(h2));
    __nv_bfloat16 q3 = __float2bfloat16(v3 - __bfloat162float(h3));
    __nv_bfloat162 ql01 = __halves2bfloat162(q0, q1);
    __nv_bfloat162 ql23 = __halves2bfloat162(q2, q3);
    uint2 ul = make_uint2(*reinterpret_cast<uint32_t*>(&ql01),
                          *reinterpret_cast<uint32_t*>(&ql23));
    reinterpret_cast<uint2*>(yl)[i4] = ul;
}

// ---------------- host launcher ----------------------------------------
extern "C" void kernel_launch(void* const* d_in, const int* in_sizes, int n_in,
                              void* d_out, int out_size) {
    const float* x = (const float*)d_in[0];
    const float* norm_g = (const float*)d_in[1];
    const float* norm_b = (const float*)d_in[2];
    const float* skip_s = (const float*)d_in[3];
    const float* proj_w = (const float*)d_in[4];
    const float* proj_b = (const float*)d_in[5];
    const float* in_proj_w = (const float*)d_in[6];
    const float* out_proj_w = (const float*)d_in[7];
    const float* conv_w[2] = {(const float*)d_in[8], (const float*)d_in[15]};
    const float* conv_b[2] = {(const float*)d_in[9], (const float*)d_in[16]};
    const float* x_proj_w[2] = {(const float*)d_in[10], (const float*)d_in[17]};
    const float* dt_w[2] = {(const float*)d_in[11], (const float*)d_in[18]};
    const float* dt_bv[2] = {(const float*)d_in[12], (const float*)d_in[19]};
    const float* A_logv[2] = {(const float*)d_in[13], (const float*)d_in[20]};
    const float* Dpv[2] = {(const float*)d_in[14], (const float*)d_in[21]};

    __nv_bfloat16 *xnh, *xnl, *yth, *ytl, *xmh, *xml;
    __nv_bfloat16 *wih, *wil, *woh, *wol, *wph, *wpl, *wxh, *wxl;
    float *xt, *xz, *xcbuf, *xdblbuf, *dtgbuf, *ybuf, *xm, *hpbuf, *h0buf;
    cudaGetSymbolAddress((void**)&xnh, g_xnh);
    cudaGetSymbolAddress((void**)&xnl, g_xnl);
    cudaGetSymbolAddress((void**)&xt, g_xt);
    cudaGetSymbolAddress((void**)&xz, g_xz);
    cudaGetSymbolAddress((void**)&xcbuf, g_xc);
    cudaGetSymbolAddress((void**)&xdblbuf, g_xdbl);
    cudaGetSymbolAddress((void**)&dtgbuf, g_dtg);
    cudaGetSymbolAddress((void**)&ybuf, g_y);
    cudaGetSymbolAddress((void**)&hpbuf, g_hp);
    cudaGetSymbolAddress((void**)&h0buf, g_h0);
    cudaGetSymbolAddress((void**)&yth, g_yth);
    cudaGetSymbolAddress((void**)&ytl, g_ytl);
    cudaGetSymbolAddress((void**)&xm, g_xm);
    cudaGetSymbolAddress((void**)&xmh, g_xmh);
    cudaGetSymbolAddress((void**)&xml, g_xml);
    cudaGetSymbolAddress((void**)&wih, g_wih);
    cudaGetSymbolAddress((void**)&wil, g_wil);
    cudaGetSymbolAddress((void**)&woh, g_woh);
    cudaGetSymbolAddress((void**)&wol, g_wol);
    cudaGetSymbolAddress((void**)&wph, g_wph);
    cudaGetSymbolAddress((void**)&wpl, g_wpl);
    cudaGetSymbolAddress((void**)&wxh, g_wxh);
    cudaGetSymbolAddress((void**)&wxl, g_wxl);
    const long SBD = (long)Bb * DI * Ll;
    const long SXD = (long)Bb * NKP * Ll;

    const int M = Bb * Ll;  // 32768
    const int TCSM = 128 * 132 * 4;  // 67584 (>= 2x32768 stages)

    cudaFuncSetAttribute(tc_gemm<true, 0, false, false>, cudaFuncAttributeMaxDynamicSharedMemorySize, TCSM);
    cudaFuncSetAttribute(tc_gemm<true, 0, true, true>, cudaFuncAttributeMaxDynamicSharedMemorySize, TCSM);
    cudaFuncSetAttribute(tc_gemm<false, 3, false, false>, cudaFuncAttributeMaxDynamicSharedMemorySize, TCSM);
    cudaFuncSetAttribute(tc_gemm<true, 2, false, false>, cudaFuncAttributeMaxDynamicSharedMemorySize, TCSM);

    wsplit_k<<<(E2 * Cc + 255) / 256, 256>>>(in_proj_w, wih, wil, E2 * Cc);   // 0
    ln1_k<<<dim3(Ll / 32, Bb), 256>>>(x, norm_g, norm_b, xnh, xnl, xt);       // 1
    tc_gemm<true, 0, false, false><<<dim3(M / 128, E2 / 128), 256, TCSM>>>(   // 2 in_proj
        xnh, xnl, wih, wil, nullptr, nullptr, nullptr,
        xz, E2, Cc, 0, 0, nullptr, nullptr, nullptr);
    conv_silu_k<<<dim3(DI, Bb), 256>>>(                                       // 3 (profiled)
        xz, conv_w[0], conv_b[0], conv_w[1], conv_b[1], xcbuf, xcbuf + SBD);
    wsplit_k<<<(NKP * DI + 255) / 256, 256>>>(x_proj_w[0], wxh, wxl, NKP * DI);            // 4
    wsplit_k<<<(NKP * DI + 255) / 256, 256>>>(x_proj_w[1], wxh + NKP * DI, wxl + NKP * DI, // 5
                                              NKP * DI);
    tc_gemm<true, 0, true, true><<<dim3(M / 128, 1, 2), 256, TCSM>>>(         // 6 x_proj
        nullptr, nullptr, wxh, wxl, wxh + NKP * DI, wxl + NKP * DI, xcbuf,
        xdblbuf, NKP, DI, SBD, SXD, nullptr, nullptr, nullptr);
    scanA_k<<<dim3(DI / 32, Bb, 2 * NPART), 128>>>(                           // 7
        xcbuf, xdblbuf, A_logv[0], A_logv[1], dt_w[0], dt_w[1],
        dt_bv[0], dt_bv[1], dtgbuf, hpbuf, SBD, SXD);
    fixup_k<<<512, 256>>>(hpbuf, h0buf);                                      // 8
    scanC_k<<<dim3(DI / 32, Bb, 2 * NPART), 128>>>(                           // 9
        xcbuf, xdblbuf, xz, dtgbuf, h0buf, A_logv[0], A_logv[1],
        Dpv[0], Dpv[1], ybuf, SBD, SXD);
    wsplit_k<<<(Cc * DI + 255) / 256, 256>>>(out_proj_w, woh, wol, Cc * DI);  // 10
    yfuse_k<<<(unsigned)(SBD / 4 / 256), 256>>>(ybuf, ybuf + SBD, yth, ytl);  // 11
    tc_gemm<false, 3, false, false><<<dim3(M / 128, Cc / 128), 256, TCSM>>>(  // 12 out_proj
        yth, ytl, woh, wol, nullptr, nullptr, nullptr,
        xm, Cc, DI, 0, 0, nullptr, xt, skip_s);
    ln2_k<<<M, 256>>>(xm, norm_g, norm_b, xmh, xml);                          // 13
    wsplit_k<<<(Cc * Cc + 255) / 256, 256>>>(proj_w, wph, wpl, Cc * Cc);      // 14
    tc_gemm<true, 2, false, false><<<dim3(M / 128, Cc / 128), 256, TCSM>>>(   // 15 proj
        xmh, xml, wph, wpl, nullptr, nullptr, nullptr,
        (float*)d_out, Cc, Cc, 0, 0, proj_b, nullptr, nullptr);
}